// round 1
// baseline (speedup 1.0000x reference)
#include <cuda_runtime.h>

#define NN 50000
#define EE 800000
#define DD 128

// ---------------- scratch (static device globals; no allocation) ----------------
__device__ float g_S[NN * DD];      // aggregation buffer (x + sum of neighbors)
__device__ float g_H[NN * DD];      // hidden buffer
__device__ float g_T[NN * DD];      // hidden buffer 2
__device__ float g_stats[3 * 256];  // per-stage: [0..127]=colsum, [128..255]=colsumsq
__device__ float g_coef[3 * 256];   // per-stage: [0..127]=a, [128..255]=b  (y = relu(a*x+b))

// ---------------- tiny kernels ----------------
__global__ void zero_stats_kernel() {
    for (int j = threadIdx.x; j < 3 * 256; j += blockDim.x) g_stats[j] = 0.f;
}

__global__ void copy_kernel(const float4* __restrict__ src, float4* __restrict__ dst, int n4) {
    int i = blockIdx.x * blockDim.x + threadIdx.x;
    if (i < n4) dst[i] = src[i];
}

// dst[row[e]] += feat[col[e]]  (one warp per edge, float4 per lane)
__global__ void edge_kernel(const float* __restrict__ feat, const int* __restrict__ row,
                            const int* __restrict__ col, float* __restrict__ dst) {
    int w = (blockIdx.x * blockDim.x + threadIdx.x) >> 5;
    if (w >= EE) return;
    int lane = threadIdx.x & 31;
    int r = __ldg(&row[w]);
    int c = __ldg(&col[w]);
    float4 v = *reinterpret_cast<const float4*>(&feat[(size_t)c * DD + lane * 4]);
    float* d = &dst[(size_t)r * DD + lane * 4];
    atomicAdd(d + 0, v.x);
    atomicAdd(d + 1, v.y);
    atomicAdd(d + 2, v.z);
    atomicAdd(d + 3, v.w);
}

// BN coefficients from accumulated column stats: a = g*rsqrt(var+eps), b = be - mean*a
__global__ void bncoef_kernel(const float* __restrict__ stats, const float* __restrict__ g,
                              const float* __restrict__ be, float* __restrict__ coef) {
    int i = threadIdx.x;  // 128 threads
    float m = stats[i] * (1.f / NN);
    float var = stats[128 + i] * (1.f / NN) - m * m;
    float a = g[i] * rsqrtf(var + 1e-5f);
    coef[i] = a;
    coef[128 + i] = be[i] - m * a;
}

// y = relu(a*t + b), written to BOTH s (aggregation init) and h (gather source)
__global__ void apply_kernel(const float4* __restrict__ t, const float* __restrict__ coef,
                             float4* __restrict__ s, float4* __restrict__ h) {
    int i = blockIdx.x * blockDim.x + threadIdx.x;
    if (i >= NN * DD / 4) return;
    int ch = (i & 31) * 4;  // DD/4 = 32 float4 per row
    float4 v = t[i];
    float a0 = __ldg(&coef[ch + 0]), b0 = __ldg(&coef[128 + ch + 0]);
    float a1 = __ldg(&coef[ch + 1]), b1 = __ldg(&coef[128 + ch + 1]);
    float a2 = __ldg(&coef[ch + 2]), b2 = __ldg(&coef[128 + ch + 2]);
    float a3 = __ldg(&coef[ch + 3]), b3 = __ldg(&coef[128 + ch + 3]);
    v.x = fmaxf(a0 * v.x + b0, 0.f);
    v.y = fmaxf(a1 * v.y + b1, 0.f);
    v.z = fmaxf(a2 * v.z + b2, 0.f);
    v.w = fmaxf(a3 * v.w + b3, 0.f);
    s[i] = v;
    h[i] = v;
}

// ---------------- GEMM: out[M,128] = pre(A)[M,128] @ W[128,128] + bias ----------------
// PRE:   apply y=relu(a*x+b) per input channel while loading A tile
// STATS: accumulate per-output-channel sum & sumsq into stats (for next BN)
template <bool PRE, bool STATS>
__global__ void __launch_bounds__(256) gemm_kernel(const float* __restrict__ A,
                                                   const float* __restrict__ W,
                                                   const float* __restrict__ bias,
                                                   const float* __restrict__ coef,
                                                   float* __restrict__ out,
                                                   float* __restrict__ stats) {
    __shared__ float As[64][32];    // A tile (rows x k-chunk)
    __shared__ float Ws[32][128];   // W tile (k-chunk x cols)
    __shared__ float csum[128], csq[128];

    int tid = threadIdx.x;
    int tx = tid & 31;        // column group: cols [tx*4, tx*4+4)
    int ty = tid >> 5;        // row group: rows ty + 8*i (i=0..7); one warp = one ty
    int rowBase = blockIdx.x * 64;

    if (STATS && tid < 128) { csum[tid] = 0.f; csq[tid] = 0.f; }

    float acc[8][4];
#pragma unroll
    for (int i = 0; i < 8; i++)
#pragma unroll
        for (int j = 0; j < 4; j++) acc[i][j] = 0.f;

    for (int kk = 0; kk < DD; kk += 32) {
        // load A tile: 64x32 floats = 512 float4, 2 per thread
#pragma unroll
        for (int i = 0; i < 2; i++) {
            int q = tid + i * 256;
            int r = q >> 3, k4 = q & 7;
            int gr = rowBase + r;
            float4 v = make_float4(0.f, 0.f, 0.f, 0.f);
            if (gr < NN) v = *reinterpret_cast<const float4*>(&A[(size_t)gr * DD + kk + k4 * 4]);
            if (PRE) {
                int ch = kk + k4 * 4;
                v.x = fmaxf(__ldg(&coef[ch + 0]) * v.x + __ldg(&coef[128 + ch + 0]), 0.f);
                v.y = fmaxf(__ldg(&coef[ch + 1]) * v.y + __ldg(&coef[128 + ch + 1]), 0.f);
                v.z = fmaxf(__ldg(&coef[ch + 2]) * v.z + __ldg(&coef[128 + ch + 2]), 0.f);
                v.w = fmaxf(__ldg(&coef[ch + 3]) * v.w + __ldg(&coef[128 + ch + 3]), 0.f);
            }
            reinterpret_cast<float4*>(&As[0][0])[q] = v;
        }
        // load W tile: 32x128 floats = 1024 float4, 4 per thread
#pragma unroll
        for (int i = 0; i < 4; i++) {
            int q = tid + i * 256;
            int k = q >> 5, c4 = q & 31;
            float4 v = *reinterpret_cast<const float4*>(&W[(size_t)(kk + k) * DD + c4 * 4]);
            reinterpret_cast<float4*>(&Ws[0][0])[q] = v;
        }
        __syncthreads();
#pragma unroll
        for (int k = 0; k < 32; k++) {
            float4 bv = *reinterpret_cast<const float4*>(&Ws[k][tx * 4]);
#pragma unroll
            for (int i = 0; i < 8; i++) {
                float a = As[ty + 8 * i][k];  // broadcast within warp
                acc[i][0] += a * bv.x;
                acc[i][1] += a * bv.y;
                acc[i][2] += a * bv.z;
                acc[i][3] += a * bv.w;
            }
        }
        __syncthreads();
    }

    float4 b4 = *reinterpret_cast<const float4*>(&bias[tx * 4]);
    float ls[4] = {0.f, 0.f, 0.f, 0.f};
    float lq[4] = {0.f, 0.f, 0.f, 0.f};
#pragma unroll
    for (int i = 0; i < 8; i++) {
        int gr = rowBase + ty + 8 * i;
        if (gr < NN) {
            float4 v;
            v.x = acc[i][0] + b4.x;
            v.y = acc[i][1] + b4.y;
            v.z = acc[i][2] + b4.z;
            v.w = acc[i][3] + b4.w;
            *reinterpret_cast<float4*>(&out[(size_t)gr * DD + tx * 4]) = v;
            if (STATS) {
                ls[0] += v.x; ls[1] += v.y; ls[2] += v.z; ls[3] += v.w;
                lq[0] += v.x * v.x; lq[1] += v.y * v.y; lq[2] += v.z * v.z; lq[3] += v.w * v.w;
            }
        }
    }
    if (STATS) {
        atomicAdd(&csum[tx * 4 + 0], ls[0]);
        atomicAdd(&csum[tx * 4 + 1], ls[1]);
        atomicAdd(&csum[tx * 4 + 2], ls[2]);
        atomicAdd(&csum[tx * 4 + 3], ls[3]);
        atomicAdd(&csq[tx * 4 + 0], lq[0]);
        atomicAdd(&csq[tx * 4 + 1], lq[1]);
        atomicAdd(&csq[tx * 4 + 2], lq[2]);
        atomicAdd(&csq[tx * 4 + 3], lq[3]);
        __syncthreads();
        if (tid < 128) {
            atomicAdd(&stats[tid], csum[tid]);
            atomicAdd(&stats[128 + tid], csq[tid]);
        }
    }
}

// ---------------- launch ----------------
extern "C" void kernel_launch(void* const* d_in, const int* in_sizes, int n_in,
                              void* d_out, int out_size) {
    const float* x     = (const float*)d_in[0];
    const int*   row   = (const int*)d_in[1];
    const int*   col   = (const int*)d_in[2];
    const float* c0_w1 = (const float*)d_in[3];
    const float* c0_b1 = (const float*)d_in[4];
    const float* c0_g  = (const float*)d_in[5];
    const float* c0_be = (const float*)d_in[6];
    const float* c0_w2 = (const float*)d_in[7];
    const float* c0_b2 = (const float*)d_in[8];
    const float* bn0_g = (const float*)d_in[9];
    const float* bn0_be= (const float*)d_in[10];
    const float* c1_w1 = (const float*)d_in[11];
    const float* c1_b1 = (const float*)d_in[12];
    const float* c1_g  = (const float*)d_in[13];
    const float* c1_be = (const float*)d_in[14];
    const float* c1_w2 = (const float*)d_in[15];
    const float* c1_b2 = (const float*)d_in[16];
    float* out = (float*)d_out;

    float *S, *H, *T, *ST, *CF;
    cudaGetSymbolAddress((void**)&S, g_S);
    cudaGetSymbolAddress((void**)&H, g_H);
    cudaGetSymbolAddress((void**)&T, g_T);
    cudaGetSymbolAddress((void**)&ST, g_stats);
    cudaGetSymbolAddress((void**)&CF, g_coef);

    const int n4 = NN * DD / 4;
    const int cpyBlocks = (n4 + 255) / 256;
    const int edgeBlocks = (EE * 32 + 255) / 256;
    const int gemmBlocks = (NN + 63) / 64;

    zero_stats_kernel<<<1, 256>>>();

    // ---- conv0 ----
    copy_kernel<<<cpyBlocks, 256>>>((const float4*)x, (float4*)S, n4);          // S = x
    edge_kernel<<<edgeBlocks, 256>>>(x, row, col, S);                           // S += scatter(x)
    gemm_kernel<false, true><<<gemmBlocks, 256>>>(S, c0_w1, c0_b1, nullptr, H, ST);      // H = S@w1+b1, stats0
    bncoef_kernel<<<1, 128>>>(ST, c0_g, c0_be, CF);                             // coef0
    gemm_kernel<true, true><<<gemmBlocks, 256>>>(H, c0_w2, c0_b2, CF, T, ST + 256);      // T = relu(bn(H))@w2+b2, stats1

    // ---- inter-layer BN+ReLU ----
    bncoef_kernel<<<1, 128>>>(ST + 256, bn0_g, bn0_be, CF + 256);
    apply_kernel<<<cpyBlocks, 256>>>((const float4*)T, CF + 256, (float4*)S, (float4*)H);  // S = H = relu(bn(T))

    // ---- conv1 ----
    edge_kernel<<<edgeBlocks, 256>>>(H, row, col, S);                           // S += scatter(H)
    gemm_kernel<false, true><<<gemmBlocks, 256>>>(S, c1_w1, c1_b1, nullptr, T, ST + 512); // T = S@w1+b1, stats2
    bncoef_kernel<<<1, 128>>>(ST + 512, c1_g, c1_be, CF + 512);
    gemm_kernel<true, false><<<gemmBlocks, 256>>>(T, c1_w2, c1_b2, CF + 512, out, nullptr); // out = relu(bn(T))@w2+b2
}

// round 2
// speedup vs baseline: 1.6968x; 1.6968x over previous
#include <cuda_runtime.h>

#define NN 50000
#define EE 800000
#define DD 128
#define MT 128   // GEMM rows per block
#define KC 16    // GEMM k-chunk
#define ASTRIDE 130  // padded row stride for k-major A tile (even -> 8B-aligned pairs, conflict-free)

// ---------------- scratch (static device globals; no allocation) ----------------
__device__ float g_S[NN * DD];
__device__ float g_H[NN * DD];
__device__ float g_T[NN * DD];
__device__ float g_stats[3 * 256];
__device__ float g_coef[3 * 256];

// ---------------- f32x2 helpers ----------------
__device__ __forceinline__ unsigned long long pack2(float lo, float hi) {
    unsigned long long r;
    asm("mov.b64 %0, {%1, %2};" : "=l"(r) : "f"(lo), "f"(hi));
    return r;
}
__device__ __forceinline__ void unpack2(unsigned long long v, float& lo, float& hi) {
    asm("mov.b64 {%0, %1}, %2;" : "=f"(lo), "=f"(hi) : "l"(v));
}
__device__ __forceinline__ void ffma2(unsigned long long& d, unsigned long long a, unsigned long long b) {
    asm("fma.rn.f32x2 %0, %1, %2, %0;" : "+l"(d) : "l"(a), "l"(b));
}

// ---------------- tiny kernels ----------------
__global__ void zero_stats_kernel() {
    for (int j = threadIdx.x; j < 3 * 256; j += blockDim.x) g_stats[j] = 0.f;
}

__global__ void copy_kernel(const float4* __restrict__ src, float4* __restrict__ dst, int n4) {
    int i = blockIdx.x * blockDim.x + threadIdx.x;
    if (i < n4) dst[i] = src[i];
}

// dst[row[e]] += feat[col[e]]  (one warp per edge, one red.v4 per lane)
__global__ void edge_kernel(const float* __restrict__ feat, const int* __restrict__ row,
                            const int* __restrict__ col, float* __restrict__ dst) {
    int w = (blockIdx.x * blockDim.x + threadIdx.x) >> 5;
    if (w >= EE) return;
    int lane = threadIdx.x & 31;
    int r = __ldg(&row[w]);
    int c = __ldg(&col[w]);
    float4 v = __ldg(reinterpret_cast<const float4*>(&feat[(size_t)c * DD + lane * 4]));
    float* d = &dst[(size_t)r * DD + lane * 4];
    asm volatile("red.global.add.v4.f32 [%0], {%1, %2, %3, %4};"
                 :: "l"(d), "f"(v.x), "f"(v.y), "f"(v.z), "f"(v.w)
                 : "memory");
}

__global__ void bncoef_kernel(const float* __restrict__ stats, const float* __restrict__ g,
                              const float* __restrict__ be, float* __restrict__ coef) {
    int i = threadIdx.x;  // 128 threads
    float m = stats[i] * (1.f / NN);
    float var = stats[128 + i] * (1.f / NN) - m * m;
    float a = g[i] * rsqrtf(var + 1e-5f);
    coef[i] = a;
    coef[128 + i] = be[i] - m * a;
}

// y = relu(a*t + b), written to BOTH s (aggregation init) and h (gather source)
__global__ void apply_kernel(const float4* __restrict__ t, const float* __restrict__ coef,
                             float4* __restrict__ s, float4* __restrict__ h) {
    int i = blockIdx.x * blockDim.x + threadIdx.x;
    if (i >= NN * DD / 4) return;
    int ch = (i & 31) * 4;
    float4 v = t[i];
    float a0 = __ldg(&coef[ch + 0]), b0 = __ldg(&coef[128 + ch + 0]);
    float a1 = __ldg(&coef[ch + 1]), b1 = __ldg(&coef[128 + ch + 1]);
    float a2 = __ldg(&coef[ch + 2]), b2 = __ldg(&coef[128 + ch + 2]);
    float a3 = __ldg(&coef[ch + 3]), b3 = __ldg(&coef[128 + ch + 3]);
    v.x = fmaxf(a0 * v.x + b0, 0.f);
    v.y = fmaxf(a1 * v.y + b1, 0.f);
    v.z = fmaxf(a2 * v.z + b2, 0.f);
    v.w = fmaxf(a3 * v.w + b3, 0.f);
    s[i] = v;
    h[i] = v;
}

// ---------------- GEMM: out[M,128] = pre(A)[M,128] @ W[128,128] + bias ----------------
// FFMA2 version: each thread owns 16 rows (8 adjacent pairs) x 4 cols.
// A tile stored k-major so a row-pair is one 8B broadcast LDS.
template <bool PRE, bool STATS>
__global__ void __launch_bounds__(256) gemm_kernel(const float* __restrict__ A,
                                                   const float* __restrict__ W,
                                                   const float* __restrict__ bias,
                                                   const float* __restrict__ coef,
                                                   float* __restrict__ out,
                                                   float* __restrict__ stats) {
    __shared__ float As[KC * ASTRIDE];  // k-major: As[k*ASTRIDE + row]
    __shared__ float Ws[KC][DD];
    __shared__ float csum[128], csq[128];

    const int tid = threadIdx.x;
    const int tx = tid & 31;   // cols [tx*4, tx*4+4)
    const int ty = tid >> 5;   // row pairs: 2*ty + 16*i
    const int rowBase = blockIdx.x * MT;

    if (STATS && tid < 128) { csum[tid] = 0.f; csq[tid] = 0.f; }

    unsigned long long acc[8][4];
#pragma unroll
    for (int i = 0; i < 8; i++)
#pragma unroll
        for (int j = 0; j < 4; j++) acc[i][j] = 0ull;

    for (int kk = 0; kk < DD; kk += KC) {
        // ---- load A tile: MT rows x KC k, coalesced float4, store k-major ----
#pragma unroll
        for (int it = 0; it < 2; it++) {
            int q = tid + it * 256;          // 0..511
            int r = q >> 2;                   // 0..127
            int k4 = q & 3;                   // 0..3 (k group of 4)
            int gr = rowBase + r;
            float4 v = make_float4(0.f, 0.f, 0.f, 0.f);
            if (gr < NN) v = *reinterpret_cast<const float4*>(&A[(size_t)gr * DD + kk + k4 * 4]);
            if (PRE) {
                int ch = kk + k4 * 4;
                v.x = fmaxf(__ldg(&coef[ch + 0]) * v.x + __ldg(&coef[128 + ch + 0]), 0.f);
                v.y = fmaxf(__ldg(&coef[ch + 1]) * v.y + __ldg(&coef[128 + ch + 1]), 0.f);
                v.z = fmaxf(__ldg(&coef[ch + 2]) * v.z + __ldg(&coef[128 + ch + 2]), 0.f);
                v.w = fmaxf(__ldg(&coef[ch + 3]) * v.w + __ldg(&coef[128 + ch + 3]), 0.f);
            }
            int kb = k4 * 4;
            As[(kb + 0) * ASTRIDE + r] = v.x;
            As[(kb + 1) * ASTRIDE + r] = v.y;
            As[(kb + 2) * ASTRIDE + r] = v.z;
            As[(kb + 3) * ASTRIDE + r] = v.w;
        }
        // ---- load W tile: KC x 128, coalesced float4 ----
#pragma unroll
        for (int it = 0; it < 2; it++) {
            int q = tid + it * 256;          // 0..511
            int k = q >> 5, c4 = q & 31;
            *reinterpret_cast<float4*>(&Ws[k][c4 * 4]) =
                *reinterpret_cast<const float4*>(&W[(size_t)(kk + k) * DD + c4 * 4]);
        }
        __syncthreads();

#pragma unroll
        for (int k = 0; k < KC; k++) {
            float4 bv = *reinterpret_cast<const float4*>(&Ws[k][tx * 4]);
            unsigned long long bx = pack2(bv.x, bv.x);
            unsigned long long by = pack2(bv.y, bv.y);
            unsigned long long bz = pack2(bv.z, bv.z);
            unsigned long long bw = pack2(bv.w, bv.w);
            const float* arow = &As[k * ASTRIDE];
#pragma unroll
            for (int i = 0; i < 8; i++) {
                unsigned long long a2 =
                    *reinterpret_cast<const unsigned long long*>(&arow[2 * ty + 16 * i]);
                ffma2(acc[i][0], a2, bx);
                ffma2(acc[i][1], a2, by);
                ffma2(acc[i][2], a2, bz);
                ffma2(acc[i][3], a2, bw);
            }
        }
        __syncthreads();
    }

    float4 b4 = *reinterpret_cast<const float4*>(&bias[tx * 4]);
    float ls[4] = {0.f, 0.f, 0.f, 0.f};
    float lq[4] = {0.f, 0.f, 0.f, 0.f};
#pragma unroll
    for (int i = 0; i < 8; i++) {
        int r0 = rowBase + 2 * ty + 16 * i;
        float lo[4], hi[4];
#pragma unroll
        for (int j = 0; j < 4; j++) unpack2(acc[i][j], lo[j], hi[j]);
        float4 v0, v1;
        v0.x = lo[0] + b4.x; v0.y = lo[1] + b4.y; v0.z = lo[2] + b4.z; v0.w = lo[3] + b4.w;
        v1.x = hi[0] + b4.x; v1.y = hi[1] + b4.y; v1.z = hi[2] + b4.z; v1.w = hi[3] + b4.w;
        if (r0 < NN) {
            *reinterpret_cast<float4*>(&out[(size_t)r0 * DD + tx * 4]) = v0;
            if (STATS) {
                ls[0] += v0.x; ls[1] += v0.y; ls[2] += v0.z; ls[3] += v0.w;
                lq[0] += v0.x * v0.x; lq[1] += v0.y * v0.y; lq[2] += v0.z * v0.z; lq[3] += v0.w * v0.w;
            }
        }
        if (r0 + 1 < NN) {
            *reinterpret_cast<float4*>(&out[(size_t)(r0 + 1) * DD + tx * 4]) = v1;
            if (STATS) {
                ls[0] += v1.x; ls[1] += v1.y; ls[2] += v1.z; ls[3] += v1.w;
                lq[0] += v1.x * v1.x; lq[1] += v1.y * v1.y; lq[2] += v1.z * v1.z; lq[3] += v1.w * v1.w;
            }
        }
    }
    if (STATS) {
        atomicAdd(&csum[tx * 4 + 0], ls[0]);
        atomicAdd(&csum[tx * 4 + 1], ls[1]);
        atomicAdd(&csum[tx * 4 + 2], ls[2]);
        atomicAdd(&csum[tx * 4 + 3], ls[3]);
        atomicAdd(&csq[tx * 4 + 0], lq[0]);
        atomicAdd(&csq[tx * 4 + 1], lq[1]);
        atomicAdd(&csq[tx * 4 + 2], lq[2]);
        atomicAdd(&csq[tx * 4 + 3], lq[3]);
        __syncthreads();
        if (tid < 128) {
            atomicAdd(&stats[tid], csum[tid]);
            atomicAdd(&stats[128 + tid], csq[tid]);
        }
    }
}

// ---------------- launch ----------------
extern "C" void kernel_launch(void* const* d_in, const int* in_sizes, int n_in,
                              void* d_out, int out_size) {
    const float* x     = (const float*)d_in[0];
    const int*   row   = (const int*)d_in[1];
    const int*   col   = (const int*)d_in[2];
    const float* c0_w1 = (const float*)d_in[3];
    const float* c0_b1 = (const float*)d_in[4];
    const float* c0_g  = (const float*)d_in[5];
    const float* c0_be = (const float*)d_in[6];
    const float* c0_w2 = (const float*)d_in[7];
    const float* c0_b2 = (const float*)d_in[8];
    const float* bn0_g = (const float*)d_in[9];
    const float* bn0_be= (const float*)d_in[10];
    const float* c1_w1 = (const float*)d_in[11];
    const float* c1_b1 = (const float*)d_in[12];
    const float* c1_g  = (const float*)d_in[13];
    const float* c1_be = (const float*)d_in[14];
    const float* c1_w2 = (const float*)d_in[15];
    const float* c1_b2 = (const float*)d_in[16];
    float* out = (float*)d_out;

    float *S, *H, *T, *ST, *CF;
    cudaGetSymbolAddress((void**)&S, g_S);
    cudaGetSymbolAddress((void**)&H, g_H);
    cudaGetSymbolAddress((void**)&T, g_T);
    cudaGetSymbolAddress((void**)&ST, g_stats);
    cudaGetSymbolAddress((void**)&CF, g_coef);

    const int n4 = NN * DD / 4;
    const int cpyBlocks = (n4 + 255) / 256;
    const int edgeBlocks = (EE * 32 + 255) / 256;
    const int gemmBlocks = (NN + MT - 1) / MT;

    zero_stats_kernel<<<1, 256>>>();

    // ---- conv0 ----
    copy_kernel<<<cpyBlocks, 256>>>((const float4*)x, (float4*)S, n4);
    edge_kernel<<<edgeBlocks, 256>>>(x, row, col, S);
    gemm_kernel<false, true><<<gemmBlocks, 256>>>(S, c0_w1, c0_b1, nullptr, H, ST);
    bncoef_kernel<<<1, 128>>>(ST, c0_g, c0_be, CF);
    gemm_kernel<true, true><<<gemmBlocks, 256>>>(H, c0_w2, c0_b2, CF, T, ST + 256);

    // ---- inter-layer BN+ReLU ----
    bncoef_kernel<<<1, 128>>>(ST + 256, bn0_g, bn0_be, CF + 256);
    apply_kernel<<<cpyBlocks, 256>>>((const float4*)T, CF + 256, (float4*)S, (float4*)H);

    // ---- conv1 ----
    edge_kernel<<<edgeBlocks, 256>>>(H, row, col, S);
    gemm_kernel<false, true><<<gemmBlocks, 256>>>(S, c1_w1, c1_b1, nullptr, T, ST + 512);
    bncoef_kernel<<<1, 128>>>(ST + 512, c1_g, c1_be, CF + 512);
    gemm_kernel<true, false><<<gemmBlocks, 256>>>(T, c1_w2, c1_b2, CF + 512, out, nullptr);
}

// round 4
// speedup vs baseline: 1.7235x; 1.0158x over previous
#include <cuda_runtime.h>
#include <cuda_bf16.h>
#include <cstdint>

#define NN 50000
#define EE 800000
#define DD 128

#define ASTR 136                      // padded row stride in bf16 (272B; conflict-free ldmatrix)
#define TILE_BYTES (128 * ASTR * 2)   // 34816 B per bf16 [128][136] image
#define WBYTES (2 * TILE_BYTES)       // hi || lo

// ---------------- scratch (static device globals; no allocation) ----------------
__device__ float g_S[NN * DD];
__device__ float g_H[NN * DD];
__device__ float g_T[NN * DD];
__device__ float g_stats[3 * 256];
__device__ float g_coef[3 * 256];
__device__ unsigned char g_WB[4][WBYTES];  // per-GEMM: [c][k] bf16 W images, hi || lo

// ---------------- helpers ----------------
__device__ __forceinline__ uint32_t smem_u32(const void* p) {
    uint32_t a;
    asm("{ .reg .u64 t; cvta.to.shared.u64 t, %1; cvt.u32.u64 %0, t; }" : "=r"(a) : "l"(p));
    return a;
}

__device__ __forceinline__ void ldmx4(uint32_t* r, uint32_t addr) {
    asm volatile("ldmatrix.sync.aligned.m8n8.x4.shared.b16 {%0,%1,%2,%3}, [%4];"
                 : "=r"(r[0]), "=r"(r[1]), "=r"(r[2]), "=r"(r[3]) : "r"(addr));
}

__device__ __forceinline__ void mma16816(float* d, const uint32_t* a, uint32_t b0, uint32_t b1) {
    asm volatile(
        "mma.sync.aligned.m16n8k16.row.col.f32.bf16.bf16.f32 "
        "{%0,%1,%2,%3}, {%4,%5,%6,%7}, {%8,%9}, {%0,%1,%2,%3};"
        : "+f"(d[0]), "+f"(d[1]), "+f"(d[2]), "+f"(d[3])
        : "r"(a[0]), "r"(a[1]), "r"(a[2]), "r"(a[3]), "r"(b0), "r"(b1));
}

// ---------------- tiny kernels ----------------
__global__ void zero_stats_kernel() {
    for (int j = threadIdx.x; j < 3 * 256; j += blockDim.x) g_stats[j] = 0.f;
}

__global__ void copy_kernel(const float4* __restrict__ src, float4* __restrict__ dst, int n4) {
    int i = blockIdx.x * blockDim.x + threadIdx.x;
    if (i < n4) dst[i] = src[i];
}

__global__ void edge_kernel(const float* __restrict__ feat, const int* __restrict__ row,
                            const int* __restrict__ col, float* __restrict__ dst) {
    int w = (blockIdx.x * blockDim.x + threadIdx.x) >> 5;
    if (w >= EE) return;
    int lane = threadIdx.x & 31;
    int r = __ldg(&row[w]);
    int c = __ldg(&col[w]);
    float4 v = __ldg(reinterpret_cast<const float4*>(&feat[(size_t)c * DD + lane * 4]));
    float* d = &dst[(size_t)r * DD + lane * 4];
    asm volatile("red.global.add.v4.f32 [%0], {%1, %2, %3, %4};"
                 :: "l"(d), "f"(v.x), "f"(v.y), "f"(v.z), "f"(v.w) : "memory");
}

__global__ void bncoef_kernel(const float* __restrict__ stats, const float* __restrict__ g,
                              const float* __restrict__ be, float* __restrict__ coef) {
    int i = threadIdx.x;
    float m = stats[i] * (1.f / NN);
    float var = stats[128 + i] * (1.f / NN) - m * m;
    float a = g[i] * rsqrtf(var + 1e-5f);
    coef[i] = a;
    coef[128 + i] = be[i] - m * a;
}

__global__ void apply_kernel(const float4* __restrict__ t, const float* __restrict__ coef,
                             float4* __restrict__ s, float4* __restrict__ h) {
    int i = blockIdx.x * blockDim.x + threadIdx.x;
    if (i >= NN * DD / 4) return;
    int ch = (i & 31) * 4;
    float4 v = t[i];
    float a0 = __ldg(&coef[ch + 0]), b0 = __ldg(&coef[128 + ch + 0]);
    float a1 = __ldg(&coef[ch + 1]), b1 = __ldg(&coef[128 + ch + 1]);
    float a2 = __ldg(&coef[ch + 2]), b2 = __ldg(&coef[128 + ch + 2]);
    float a3 = __ldg(&coef[ch + 3]), b3 = __ldg(&coef[128 + ch + 3]);
    v.x = fmaxf(a0 * v.x + b0, 0.f);
    v.y = fmaxf(a1 * v.y + b1, 0.f);
    v.z = fmaxf(a2 * v.z + b2, 0.f);
    v.w = fmaxf(a3 * v.w + b3, 0.f);
    s[i] = v;
    h[i] = v;
}

// W prep: W[k][c] f32 -> [c][k] padded bf16 images (hi at 0, lo at TILE_BYTES)
__global__ void wprep_kernel(const float* __restrict__ W, unsigned char* __restrict__ WB) {
    int idx = blockIdx.x * 256 + threadIdx.x;  // 16384
    int k = idx >> 7, c = idx & 127;
    float w = W[idx];
    __nv_bfloat16 h = __float2bfloat16(w);
    __nv_bfloat16 l = __float2bfloat16(w - __bfloat162float(h));
    uint32_t off = ((uint32_t)c * ASTR + (uint32_t)k) * 2;
    *reinterpret_cast<__nv_bfloat16*>(WB + off) = h;
    *reinterpret_cast<__nv_bfloat16*>(WB + TILE_BYTES + off) = l;
}

// column sum & sumsq over NN rows (L2-bound pass)
__global__ void stats_kernel(const float4* __restrict__ buf, float* __restrict__ st) {
    int c4 = threadIdx.x & 31, rt = threadIdx.x >> 5;
    float ls[4] = {0.f, 0.f, 0.f, 0.f}, lq[4] = {0.f, 0.f, 0.f, 0.f};
    for (int r = blockIdx.x * 8 + rt; r < NN; r += gridDim.x * 8) {
        float4 v = buf[(size_t)r * 32 + c4];
        ls[0] += v.x; ls[1] += v.y; ls[2] += v.z; ls[3] += v.w;
        lq[0] += v.x * v.x; lq[1] += v.y * v.y; lq[2] += v.z * v.z; lq[3] += v.w * v.w;
    }
    __shared__ float ss[8][128], sq[8][128];
#pragma unroll
    for (int j = 0; j < 4; j++) { ss[rt][c4 * 4 + j] = ls[j]; sq[rt][c4 * 4 + j] = lq[j]; }
    __syncthreads();
    if (rt == 0) {
#pragma unroll
        for (int j = 0; j < 4; j++) {
            float a = 0.f, b = 0.f;
#pragma unroll
            for (int t = 0; t < 8; t++) { a += ss[t][c4 * 4 + j]; b += sq[t][c4 * 4 + j]; }
            atomicAdd(&st[c4 * 4 + j], a);
            atomicAdd(&st[128 + c4 * 4 + j], b);
        }
    }
}

// ---------------- tensor-core GEMM (mma.sync bf16, 3-pass compensated) ----------------
// out[128,128] = pre(A)[128,128] @ W[128,128] + bias
template <bool PRE>
__global__ void __launch_bounds__(256, 1) gemm_tc(const float* __restrict__ A,
                                                  const unsigned char* __restrict__ WB,
                                                  const float* __restrict__ bias,
                                                  const float* __restrict__ coef,
                                                  float* __restrict__ out) {
    extern __shared__ unsigned char sm[];
    // layout: sAh[0, 34816) | sAl | sBh | sBl
    unsigned char* sA = sm;
    unsigned char* sB = sm + 2 * TILE_BYTES;
    const uint32_t sbase = smem_u32(sm);
    const int tid = threadIdx.x, wid = tid >> 5, lane = tid & 31;
    const int rowBase = blockIdx.x * 128;

    // ---- B fill: linear copy of pre-swizzled hi||lo images (69632 B) ----
    {
        const uint4* src = reinterpret_cast<const uint4*>(WB);
        uint4* dst = reinterpret_cast<uint4*>(sB);
#pragma unroll
        for (int i = 0; i < 17; i++) dst[tid + i * 256] = src[tid + i * 256];
    }
    // ---- A fill: warp w covers rows {8*it + w}; lane covers k = lane*4.. ----
    {
        const int k0 = lane * 4;
        float ca[4], cb[4];
        if (PRE) {
#pragma unroll
            for (int j = 0; j < 4; j++) {
                ca[j] = __ldg(&coef[k0 + j]);
                cb[j] = __ldg(&coef[128 + k0 + j]);
            }
        }
#pragma unroll 4
        for (int it = 0; it < 16; it++) {
            int r = it * 8 + wid;
            int gr = rowBase + r;
            float4 v = make_float4(0.f, 0.f, 0.f, 0.f);
            if (gr < NN) {
                v = *reinterpret_cast<const float4*>(&A[(size_t)gr * DD + k0]);
                if (PRE) {
                    v.x = fmaxf(ca[0] * v.x + cb[0], 0.f);
                    v.y = fmaxf(ca[1] * v.y + cb[1], 0.f);
                    v.z = fmaxf(ca[2] * v.z + cb[2], 0.f);
                    v.w = fmaxf(ca[3] * v.w + cb[3], 0.f);
                }
            }
            __nv_bfloat16 hx = __float2bfloat16(v.x), hy = __float2bfloat16(v.y);
            __nv_bfloat16 hz = __float2bfloat16(v.z), hw = __float2bfloat16(v.w);
            __nv_bfloat16 lx = __float2bfloat16(v.x - __bfloat162float(hx));
            __nv_bfloat16 ly = __float2bfloat16(v.y - __bfloat162float(hy));
            __nv_bfloat16 lz = __float2bfloat16(v.z - __bfloat162float(hz));
            __nv_bfloat16 lw = __float2bfloat16(v.w - __bfloat162float(hw));
            uint32_t h01 = ((uint32_t)__bfloat16_as_ushort(hy) << 16) | __bfloat16_as_ushort(hx);
            uint32_t h23 = ((uint32_t)__bfloat16_as_ushort(hw) << 16) | __bfloat16_as_ushort(hz);
            uint32_t l01 = ((uint32_t)__bfloat16_as_ushort(ly) << 16) | __bfloat16_as_ushort(lx);
            uint32_t l23 = ((uint32_t)__bfloat16_as_ushort(lw) << 16) | __bfloat16_as_ushort(lz);
            uint32_t off = ((uint32_t)r * ASTR + (uint32_t)k0) * 2;
            *reinterpret_cast<uint2*>(sA + off) = make_uint2(h01, h23);
            *reinterpret_cast<uint2*>(sA + TILE_BYTES + off) = make_uint2(l01, l23);
        }
    }
    __syncthreads();

    // ---- warp/fragment setup ----
    const int wr = wid & 3;       // M quadrant: rows wr*32 .. +31
    const int wc = wid >> 2;      // N half: cols wc*64 .. +63
    const int mbase = wr * 32;
    const int nbase = wc * 64;

    // per-lane ldmatrix byte offsets
    const uint32_t aoff = (uint32_t)(lane & 15) * (ASTR * 2) + (uint32_t)(lane >> 4) * 16;
    const uint32_t boff = ((uint32_t)((lane >> 4) * 8 + (lane & 7))) * (ASTR * 2)
                        + (uint32_t)((lane >> 3) & 1) * 16;

    float acc[2][8][4];
#pragma unroll
    for (int mt = 0; mt < 2; mt++)
#pragma unroll
        for (int nt = 0; nt < 8; nt++)
#pragma unroll
            for (int j = 0; j < 4; j++) acc[mt][nt][j] = 0.f;

    const uint32_t aB[3] = { sbase, sbase, sbase + TILE_BYTES };                       // Ah, Ah, Al
    const uint32_t bB[3] = { sbase + 2u * TILE_BYTES, sbase + 3u * TILE_BYTES,
                             sbase + 2u * TILE_BYTES };                                // Bh, Bl, Bh

#pragma unroll 1
    for (int pass = 0; pass < 3; pass++) {
        const uint32_t pa = aB[pass] + (uint32_t)mbase * (ASTR * 2) + aoff;
        const uint32_t pb = bB[pass] + (uint32_t)nbase * (ASTR * 2) + boff;
#pragma unroll
        for (int ks = 0; ks < 8; ks++) {
            const uint32_t kb = (uint32_t)ks * 32;  // 16 bf16 = 32 bytes
            uint32_t a[2][4];
            ldmx4(a[0], pa + kb);
            ldmx4(a[1], pa + 16u * (ASTR * 2) + kb);
            uint32_t b[4][4];
#pragma unroll
            for (int q = 0; q < 4; q++) ldmx4(b[q], pb + (uint32_t)q * 16u * (ASTR * 2) + kb);
#pragma unroll
            for (int mt = 0; mt < 2; mt++)
#pragma unroll
                for (int nt = 0; nt < 8; nt++)
                    mma16816(acc[mt][nt], a[mt], b[nt >> 1][(nt & 1) * 2], b[nt >> 1][(nt & 1) * 2 + 1]);
        }
    }

    // ---- epilogue: add bias, store ----
    const int g = lane >> 2, t = lane & 3;
#pragma unroll
    for (int mt = 0; mt < 2; mt++) {
#pragma unroll
        for (int half = 0; half < 2; half++) {  // d0/d1 (row g) vs d2/d3 (row g+8)
            int r = rowBase + mbase + mt * 16 + g + half * 8;
            if (r < NN) {
#pragma unroll
                for (int nt = 0; nt < 8; nt++) {
                    int c = nbase + nt * 8 + t * 2;
                    float2 bb = *reinterpret_cast<const float2*>(&bias[c]);
                    float2 o;
                    o.x = acc[mt][nt][half * 2 + 0] + bb.x;
                    o.y = acc[mt][nt][half * 2 + 1] + bb.y;
                    *reinterpret_cast<float2*>(&out[(size_t)r * DD + c]) = o;
                }
            }
        }
    }
}

// ---------------- launch ----------------
extern "C" void kernel_launch(void* const* d_in, const int* in_sizes, int n_in,
                              void* d_out, int out_size) {
    const float* x     = (const float*)d_in[0];
    const int*   row   = (const int*)d_in[1];
    const int*   col   = (const int*)d_in[2];
    const float* c0_w1 = (const float*)d_in[3];
    const float* c0_b1 = (const float*)d_in[4];
    const float* c0_g  = (const float*)d_in[5];
    const float* c0_be = (const float*)d_in[6];
    const float* c0_w2 = (const float*)d_in[7];
    const float* c0_b2 = (const float*)d_in[8];
    const float* bn0_g = (const float*)d_in[9];
    const float* bn0_be= (const float*)d_in[10];
    const float* c1_w1 = (const float*)d_in[11];
    const float* c1_b1 = (const float*)d_in[12];
    const float* c1_g  = (const float*)d_in[13];
    const float* c1_be = (const float*)d_in[14];
    const float* c1_w2 = (const float*)d_in[15];
    const float* c1_b2 = (const float*)d_in[16];
    float* out = (float*)d_out;

    float *S, *H, *T, *ST, *CF;
    unsigned char* WB;
    cudaGetSymbolAddress((void**)&S, g_S);
    cudaGetSymbolAddress((void**)&H, g_H);
    cudaGetSymbolAddress((void**)&T, g_T);
    cudaGetSymbolAddress((void**)&ST, g_stats);
    cudaGetSymbolAddress((void**)&CF, g_coef);
    cudaGetSymbolAddress((void**)&WB, g_WB);

    const int SMEMSZ = 4 * TILE_BYTES;  // 139264
    cudaFuncSetAttribute(gemm_tc<false>, cudaFuncAttributeMaxDynamicSharedMemorySize, SMEMSZ);
    cudaFuncSetAttribute(gemm_tc<true>, cudaFuncAttributeMaxDynamicSharedMemorySize, SMEMSZ);

    const int n4 = NN * DD / 4;
    const int cpyBlocks = (n4 + 255) / 256;
    const int edgeBlocks = (EE * 32 + 255) / 256;
    const int gemmBlocks = (NN + 127) / 128;

    zero_stats_kernel<<<1, 256>>>();
    wprep_kernel<<<64, 256>>>(c0_w1, WB + 0 * WBYTES);
    wprep_kernel<<<64, 256>>>(c0_w2, WB + 1 * WBYTES);
    wprep_kernel<<<64, 256>>>(c1_w1, WB + 2 * WBYTES);
    wprep_kernel<<<64, 256>>>(c1_w2, WB + 3 * WBYTES);

    // ---- conv0 ----
    copy_kernel<<<cpyBlocks, 256>>>((const float4*)x, (float4*)S, n4);
    edge_kernel<<<edgeBlocks, 256>>>(x, row, col, S);
    gemm_tc<false><<<gemmBlocks, 256, SMEMSZ>>>(S, WB + 0 * WBYTES, c0_b1, nullptr, H);
    stats_kernel<<<256, 256>>>((const float4*)H, ST);
    bncoef_kernel<<<1, 128>>>(ST, c0_g, c0_be, CF);
    gemm_tc<true><<<gemmBlocks, 256, SMEMSZ>>>(H, WB + 1 * WBYTES, c0_b2, CF, T);

    // ---- inter-layer BN+ReLU ----
    stats_kernel<<<256, 256>>>((const float4*)T, ST + 256);
    bncoef_kernel<<<1, 128>>>(ST + 256, bn0_g, bn0_be, CF + 256);
    apply_kernel<<<cpyBlocks, 256>>>((const float4*)T, CF + 256, (float4*)S, (float4*)H);

    // ---- conv1 ----
    edge_kernel<<<edgeBlocks, 256>>>(H, row, col, S);
    gemm_tc<false><<<gemmBlocks, 256, SMEMSZ>>>(S, WB + 2 * WBYTES, c1_b1, nullptr, T);
    stats_kernel<<<256, 256>>>((const float4*)T, ST + 512);
    bncoef_kernel<<<1, 128>>>(ST + 512, c1_g, c1_be, CF + 512);
    gemm_tc<true><<<gemmBlocks, 256, SMEMSZ>>>(T, WB + 3 * WBYTES, c1_b2, CF + 512, out);
}

// round 5
// speedup vs baseline: 2.1700x; 1.2590x over previous
#include <cuda_runtime.h>
#include <cuda_bf16.h>
#include <cstdint>

#define NN 50000
#define EE 800000
#define DD 128

#define ASTR 136                      // padded row stride in bf16 (272B; conflict-free ldmatrix)
#define TILE_BYTES (128 * ASTR * 2)   // 34816 B per bf16 [128][136] image
#define WBYTES (2 * TILE_BYTES)       // hi || lo

// ---------------- scratch (static device globals; no allocation) ----------------
__device__ float g_S[NN * DD];
__device__ float g_H[NN * DD];
__device__ float g_T[NN * DD];
__device__ float g_stats[3 * 256];
__device__ float g_coef[3 * 256];
__device__ unsigned char g_WB[4][WBYTES];
__device__ int g_deg[NN];
__device__ int g_cur[NN];
__device__ int g_off[NN + 1];
__device__ int g_adj[EE];

// ---------------- helpers ----------------
__device__ __forceinline__ uint32_t smem_u32(const void* p) {
    uint32_t a;
    asm("{ .reg .u64 t; cvta.to.shared.u64 t, %1; cvt.u32.u64 %0, t; }" : "=r"(a) : "l"(p));
    return a;
}

__device__ __forceinline__ void ldmx4(uint32_t* r, uint32_t addr) {
    asm volatile("ldmatrix.sync.aligned.m8n8.x4.shared.b16 {%0,%1,%2,%3}, [%4];"
                 : "=r"(r[0]), "=r"(r[1]), "=r"(r[2]), "=r"(r[3]) : "r"(addr));
}

__device__ __forceinline__ void mma16816(float* d, const uint32_t* a, uint32_t b0, uint32_t b1) {
    asm volatile(
        "mma.sync.aligned.m16n8k16.row.col.f32.bf16.bf16.f32 "
        "{%0,%1,%2,%3}, {%4,%5,%6,%7}, {%8,%9}, {%0,%1,%2,%3};"
        : "+f"(d[0]), "+f"(d[1]), "+f"(d[2]), "+f"(d[3])
        : "r"(a[0]), "r"(a[1]), "r"(a[2]), "r"(a[3]), "r"(b0), "r"(b1));
}

// ---------------- prep: zero stats/deg/cur + split all 4 W into bf16 hi/lo images ----------------
__global__ void prep_kernel(const float* __restrict__ w0, const float* __restrict__ w1,
                            const float* __restrict__ w2, const float* __restrict__ w3) {
    int b = blockIdx.x;  // 0..255
    // zeroing: deg + cur (100000 ints) spread over grid
    for (int z = b * 256 + threadIdx.x; z < 2 * NN; z += 256 * 256) {
        if (z < NN) g_deg[z] = 0;
        else g_cur[z - NN] = 0;
    }
    if (b == 0) {
        for (int j = threadIdx.x; j < 3 * 256; j += 256) g_stats[j] = 0.f;
    }
    // W split: 64 blocks per weight matrix
    int widx = b >> 6;
    const float* W = (widx == 0) ? w0 : (widx == 1) ? w1 : (widx == 2) ? w2 : w3;
    unsigned char* WB = g_WB[widx];
    int idx = (b & 63) * 256 + threadIdx.x;  // 0..16383
    int k = idx >> 7, c = idx & 127;
    float w = W[idx];
    __nv_bfloat16 h = __float2bfloat16(w);
    __nv_bfloat16 l = __float2bfloat16(w - __bfloat162float(h));
    uint32_t off = ((uint32_t)c * ASTR + (uint32_t)k) * 2;
    *reinterpret_cast<__nv_bfloat16*>(WB + off) = h;
    *reinterpret_cast<__nv_bfloat16*>(WB + TILE_BYTES + off) = l;
}

// ---------------- CSR build ----------------
__global__ void hist_kernel(const int* __restrict__ row) {
    int e = blockIdx.x * 256 + threadIdx.x;
    if (e < EE) atomicAdd(&g_deg[__ldg(&row[e])], 1);
}

__global__ void scan_kernel() {  // single block, 1024 threads
    __shared__ int ps[1024];
    const int t = threadIdx.x;
    const int CH = (NN + 1023) / 1024;  // 49
    const int base = t * CH;
    int s = 0;
#pragma unroll 7
    for (int i = 0; i < CH; i++) {
        int n = base + i;
        if (n < NN) s += g_deg[n];
    }
    ps[t] = s;
    __syncthreads();
    for (int d = 1; d < 1024; d <<= 1) {
        int v = (t >= d) ? ps[t - d] : 0;
        __syncthreads();
        ps[t] += v;
        __syncthreads();
    }
    int run = (t == 0) ? 0 : ps[t - 1];
#pragma unroll 7
    for (int i = 0; i < CH; i++) {
        int n = base + i;
        if (n < NN) {
            g_off[n] = run;
            run += g_deg[n];
        }
    }
    if (t == 1023) g_off[NN] = run;
}

__global__ void fill_kernel(const int* __restrict__ row, const int* __restrict__ col) {
    int e = blockIdx.x * 256 + threadIdx.x;
    if (e >= EE) return;
    int r = __ldg(&row[e]);
    int p = atomicAdd(&g_cur[r], 1);
    g_adj[g_off[r] + p] = __ldg(&col[e]);
}

// ---------------- gather: dst[i] = pre(feat[i]) + sum_j pre(feat[adj[j]]) ----------------
template <bool PRE>
__global__ void gather_kernel(const float* __restrict__ feat, const float* __restrict__ coef,
                              float* __restrict__ dst) {
    int node = (blockIdx.x * blockDim.x + threadIdx.x) >> 5;
    if (node >= NN) return;
    const int lane = threadIdx.x & 31;
    const int k0 = lane * 4;

    float4 ca, cb;
    if (PRE) {
        ca = __ldg(reinterpret_cast<const float4*>(&coef[k0]));
        cb = __ldg(reinterpret_cast<const float4*>(&coef[128 + k0]));
    }
#define PREV(v)                                      \
    if (PRE) {                                       \
        (v).x = fmaxf(ca.x * (v).x + cb.x, 0.f);     \
        (v).y = fmaxf(ca.y * (v).y + cb.y, 0.f);     \
        (v).z = fmaxf(ca.z * (v).z + cb.z, 0.f);     \
        (v).w = fmaxf(ca.w * (v).w + cb.w, 0.f);     \
    }

    float4 acc = __ldg(reinterpret_cast<const float4*>(&feat[(size_t)node * DD + k0]));
    PREV(acc);

    const int s = __ldg(&g_off[node]);
    const int e = __ldg(&g_off[node + 1]);
    int j = s;
    for (; j + 4 <= e; j += 4) {
        int c0 = __ldg(&g_adj[j + 0]);
        int c1 = __ldg(&g_adj[j + 1]);
        int c2 = __ldg(&g_adj[j + 2]);
        int c3 = __ldg(&g_adj[j + 3]);
        float4 v0 = __ldg(reinterpret_cast<const float4*>(&feat[(size_t)c0 * DD + k0]));
        float4 v1 = __ldg(reinterpret_cast<const float4*>(&feat[(size_t)c1 * DD + k0]));
        float4 v2 = __ldg(reinterpret_cast<const float4*>(&feat[(size_t)c2 * DD + k0]));
        float4 v3 = __ldg(reinterpret_cast<const float4*>(&feat[(size_t)c3 * DD + k0]));
        PREV(v0); PREV(v1); PREV(v2); PREV(v3);
        acc.x += (v0.x + v1.x) + (v2.x + v3.x);
        acc.y += (v0.y + v1.y) + (v2.y + v3.y);
        acc.z += (v0.z + v1.z) + (v2.z + v3.z);
        acc.w += (v0.w + v1.w) + (v2.w + v3.w);
    }
    for (; j < e; j++) {
        int c = __ldg(&g_adj[j]);
        float4 v = __ldg(reinterpret_cast<const float4*>(&feat[(size_t)c * DD + k0]));
        PREV(v);
        acc.x += v.x; acc.y += v.y; acc.z += v.z; acc.w += v.w;
    }
    *reinterpret_cast<float4*>(&dst[(size_t)node * DD + k0]) = acc;
#undef PREV
}

// ---------------- BN helpers ----------------
__global__ void bncoef_kernel(const float* __restrict__ stats, const float* __restrict__ g,
                              const float* __restrict__ be, float* __restrict__ coef) {
    int i = threadIdx.x;
    float m = stats[i] * (1.f / NN);
    float var = stats[128 + i] * (1.f / NN) - m * m;
    float a = g[i] * rsqrtf(var + 1e-5f);
    coef[i] = a;
    coef[128 + i] = be[i] - m * a;
}

__global__ void stats_kernel(const float4* __restrict__ buf, float* __restrict__ st) {
    int c4 = threadIdx.x & 31, rt = threadIdx.x >> 5;
    float ls[4] = {0.f, 0.f, 0.f, 0.f}, lq[4] = {0.f, 0.f, 0.f, 0.f};
    for (int r = blockIdx.x * 8 + rt; r < NN; r += gridDim.x * 8) {
        float4 v = buf[(size_t)r * 32 + c4];
        ls[0] += v.x; ls[1] += v.y; ls[2] += v.z; ls[3] += v.w;
        lq[0] += v.x * v.x; lq[1] += v.y * v.y; lq[2] += v.z * v.z; lq[3] += v.w * v.w;
    }
    __shared__ float ss[8][128], sq[8][128];
#pragma unroll
    for (int j = 0; j < 4; j++) { ss[rt][c4 * 4 + j] = ls[j]; sq[rt][c4 * 4 + j] = lq[j]; }
    __syncthreads();
    if (rt == 0) {
#pragma unroll
        for (int j = 0; j < 4; j++) {
            float a = 0.f, b = 0.f;
#pragma unroll
            for (int t = 0; t < 8; t++) { a += ss[t][c4 * 4 + j]; b += sq[t][c4 * 4 + j]; }
            atomicAdd(&st[c4 * 4 + j], a);
            atomicAdd(&st[128 + c4 * 4 + j], b);
        }
    }
}

// ---------------- tensor-core GEMM (mma.sync bf16, 3-pass compensated) ----------------
template <bool PRE>
__global__ void __launch_bounds__(256, 1) gemm_tc(const float* __restrict__ A,
                                                  const unsigned char* __restrict__ WB,
                                                  const float* __restrict__ bias,
                                                  const float* __restrict__ coef,
                                                  float* __restrict__ out) {
    extern __shared__ unsigned char sm[];
    unsigned char* sA = sm;
    unsigned char* sB = sm + 2 * TILE_BYTES;
    const uint32_t sbase = smem_u32(sm);
    const int tid = threadIdx.x, wid = tid >> 5, lane = tid & 31;
    const int rowBase = blockIdx.x * 128;

    {
        const uint4* src = reinterpret_cast<const uint4*>(WB);
        uint4* dst = reinterpret_cast<uint4*>(sB);
#pragma unroll
        for (int i = 0; i < 17; i++) dst[tid + i * 256] = src[tid + i * 256];
    }
    {
        const int k0 = lane * 4;
        float ca[4], cb[4];
        if (PRE) {
#pragma unroll
            for (int j = 0; j < 4; j++) {
                ca[j] = __ldg(&coef[k0 + j]);
                cb[j] = __ldg(&coef[128 + k0 + j]);
            }
        }
#pragma unroll 4
        for (int it = 0; it < 16; it++) {
            int r = it * 8 + wid;
            int gr = rowBase + r;
            float4 v = make_float4(0.f, 0.f, 0.f, 0.f);
            if (gr < NN) {
                v = *reinterpret_cast<const float4*>(&A[(size_t)gr * DD + k0]);
                if (PRE) {
                    v.x = fmaxf(ca[0] * v.x + cb[0], 0.f);
                    v.y = fmaxf(ca[1] * v.y + cb[1], 0.f);
                    v.z = fmaxf(ca[2] * v.z + cb[2], 0.f);
                    v.w = fmaxf(ca[3] * v.w + cb[3], 0.f);
                }
            }
            __nv_bfloat16 hx = __float2bfloat16(v.x), hy = __float2bfloat16(v.y);
            __nv_bfloat16 hz = __float2bfloat16(v.z), hw = __float2bfloat16(v.w);
            __nv_bfloat16 lx = __float2bfloat16(v.x - __bfloat162float(hx));
            __nv_bfloat16 ly = __float2bfloat16(v.y - __bfloat162float(hy));
            __nv_bfloat16 lz = __float2bfloat16(v.z - __bfloat162float(hz));
            __nv_bfloat16 lw = __float2bfloat16(v.w - __bfloat162float(hw));
            uint32_t h01 = ((uint32_t)__bfloat16_as_ushort(hy) << 16) | __bfloat16_as_ushort(hx);
            uint32_t h23 = ((uint32_t)__bfloat16_as_ushort(hw) << 16) | __bfloat16_as_ushort(hz);
            uint32_t l01 = ((uint32_t)__bfloat16_as_ushort(ly) << 16) | __bfloat16_as_ushort(lx);
            uint32_t l23 = ((uint32_t)__bfloat16_as_ushort(lw) << 16) | __bfloat16_as_ushort(lz);
            uint32_t off = ((uint32_t)r * ASTR + (uint32_t)k0) * 2;
            *reinterpret_cast<uint2*>(sA + off) = make_uint2(h01, h23);
            *reinterpret_cast<uint2*>(sA + TILE_BYTES + off) = make_uint2(l01, l23);
        }
    }
    __syncthreads();

    const int wr = wid & 3;
    const int wc = wid >> 2;
    const int mbase = wr * 32;
    const int nbase = wc * 64;

    const uint32_t aoff = (uint32_t)(lane & 15) * (ASTR * 2) + (uint32_t)(lane >> 4) * 16;
    const uint32_t boff = ((uint32_t)((lane >> 4) * 8 + (lane & 7))) * (ASTR * 2)
                        + (uint32_t)((lane >> 3) & 1) * 16;

    float acc[2][8][4];
#pragma unroll
    for (int mt = 0; mt < 2; mt++)
#pragma unroll
        for (int nt = 0; nt < 8; nt++)
#pragma unroll
            for (int j = 0; j < 4; j++) acc[mt][nt][j] = 0.f;

    const uint32_t aB[3] = { sbase, sbase, sbase + TILE_BYTES };
    const uint32_t bB[3] = { sbase + 2u * TILE_BYTES, sbase + 3u * TILE_BYTES,
                             sbase + 2u * TILE_BYTES };

#pragma unroll 1
    for (int pass = 0; pass < 3; pass++) {
        const uint32_t pa = aB[pass] + (uint32_t)mbase * (ASTR * 2) + aoff;
        const uint32_t pb = bB[pass] + (uint32_t)nbase * (ASTR * 2) + boff;
#pragma unroll
        for (int ks = 0; ks < 8; ks++) {
            const uint32_t kb = (uint32_t)ks * 32;
            uint32_t a[2][4];
            ldmx4(a[0], pa + kb);
            ldmx4(a[1], pa + 16u * (ASTR * 2) + kb);
            uint32_t b[4][4];
#pragma unroll
            for (int q = 0; q < 4; q++) ldmx4(b[q], pb + (uint32_t)q * 16u * (ASTR * 2) + kb);
#pragma unroll
            for (int mt = 0; mt < 2; mt++)
#pragma unroll
                for (int nt = 0; nt < 8; nt++)
                    mma16816(acc[mt][nt], a[mt], b[nt >> 1][(nt & 1) * 2], b[nt >> 1][(nt & 1) * 2 + 1]);
        }
    }

    const int g = lane >> 2, t = lane & 3;
#pragma unroll
    for (int mt = 0; mt < 2; mt++) {
#pragma unroll
        for (int half = 0; half < 2; half++) {
            int r = rowBase + mbase + mt * 16 + g + half * 8;
            if (r < NN) {
#pragma unroll
                for (int nt = 0; nt < 8; nt++) {
                    int c = nbase + nt * 8 + t * 2;
                    float2 bb = *reinterpret_cast<const float2*>(&bias[c]);
                    float2 o;
                    o.x = acc[mt][nt][half * 2 + 0] + bb.x;
                    o.y = acc[mt][nt][half * 2 + 1] + bb.y;
                    *reinterpret_cast<float2*>(&out[(size_t)r * DD + c]) = o;
                }
            }
        }
    }
}

// ---------------- launch ----------------
extern "C" void kernel_launch(void* const* d_in, const int* in_sizes, int n_in,
                              void* d_out, int out_size) {
    const float* x     = (const float*)d_in[0];
    const int*   row   = (const int*)d_in[1];
    const int*   col   = (const int*)d_in[2];
    const float* c0_w1 = (const float*)d_in[3];
    const float* c0_b1 = (const float*)d_in[4];
    const float* c0_g  = (const float*)d_in[5];
    const float* c0_be = (const float*)d_in[6];
    const float* c0_w2 = (const float*)d_in[7];
    const float* c0_b2 = (const float*)d_in[8];
    const float* bn0_g = (const float*)d_in[9];
    const float* bn0_be= (const float*)d_in[10];
    const float* c1_w1 = (const float*)d_in[11];
    const float* c1_b1 = (const float*)d_in[12];
    const float* c1_g  = (const float*)d_in[13];
    const float* c1_be = (const float*)d_in[14];
    const float* c1_w2 = (const float*)d_in[15];
    const float* c1_b2 = (const float*)d_in[16];
    float* out = (float*)d_out;

    float *S, *H, *T, *ST, *CF;
    unsigned char* WB;
    cudaGetSymbolAddress((void**)&S, g_S);
    cudaGetSymbolAddress((void**)&H, g_H);
    cudaGetSymbolAddress((void**)&T, g_T);
    cudaGetSymbolAddress((void**)&ST, g_stats);
    cudaGetSymbolAddress((void**)&CF, g_coef);
    cudaGetSymbolAddress((void**)&WB, g_WB);

    const int SMEMSZ = 4 * TILE_BYTES;  // 139264
    cudaFuncSetAttribute(gemm_tc<false>, cudaFuncAttributeMaxDynamicSharedMemorySize, SMEMSZ);
    cudaFuncSetAttribute(gemm_tc<true>, cudaFuncAttributeMaxDynamicSharedMemorySize, SMEMSZ);

    const int histBlocks = (EE + 255) / 256;
    const int gatherBlocks = (NN * 32 + 255) / 256;
    const int gemmBlocks = (NN + 127) / 128;

    // prep + CSR build (CSR reused by both convs)
    prep_kernel<<<256, 256>>>(c0_w1, c0_w2, c1_w1, c1_w2);
    hist_kernel<<<histBlocks, 256>>>(row);
    scan_kernel<<<1, 1024>>>();
    fill_kernel<<<histBlocks, 256>>>(row, col);

    // ---- conv0 ----
    gather_kernel<false><<<gatherBlocks, 256>>>(x, nullptr, S);          // S = x + agg(x)
    gemm_tc<false><<<gemmBlocks, 256, SMEMSZ>>>(S, WB + 0 * WBYTES, c0_b1, nullptr, H);
    stats_kernel<<<256, 256>>>((const float4*)H, ST);
    bncoef_kernel<<<1, 128>>>(ST, c0_g, c0_be, CF);
    gemm_tc<true><<<gemmBlocks, 256, SMEMSZ>>>(H, WB + 1 * WBYTES, c0_b2, CF, T);

    // ---- inter-layer BN+ReLU fused into gather ----
    stats_kernel<<<256, 256>>>((const float4*)T, ST + 256);
    bncoef_kernel<<<1, 128>>>(ST + 256, bn0_g, bn0_be, CF + 256);

    // ---- conv1 ----
    gather_kernel<true><<<gatherBlocks, 256>>>(T, CF + 256, S);          // S = h + agg(h), h=relu(bn0(T))
    gemm_tc<false><<<gemmBlocks, 256, SMEMSZ>>>(S, WB + 2 * WBYTES, c1_b1, nullptr, H);
    stats_kernel<<<256, 256>>>((const float4*)H, ST + 512);
    bncoef_kernel<<<1, 128>>>(ST + 512, c1_g, c1_be, CF + 512);
    gemm_tc<true><<<gemmBlocks, 256, SMEMSZ>>>(H, WB + 3 * WBYTES, c1_b2, CF + 512, out);
}